// round 11
// baseline (speedup 1.0000x reference)
#include <cuda_runtime.h>
#include <cuda_bf16.h>

// ConeProjection: out[b,k] = P[k]^T * sigma[b] * P[k]
//   sigma[a][c] = (vn·w_a)(vn·w_c) - alpha*(w_a·w_c)
//   w0 = R[:,0], w1 = R[:,1], w2 = t - eyes, vn = v/max(||v||,1e-14)
//   P[k] = ((ki-6)/6, (kj-6)/6, 1),  k = 13*ki + kj
//
// R6 inner loop (fastest measured: full per-thread geometry tables in regs,
// 5 FFMA + predicated streaming STG per pass, regs ~63) combined with
// single-wave packing done by GRID SHAPE instead of register squeezing:
// at ~63 regs -> 4 blocks/SM -> 592 resident CTAs; launch 512 blocks and give
// each warp TWO groups of 16 batches (512*8*2*16 = 131072 exactly), so the
// whole grid is co-resident in one balanced wave.

#define K_GRID  169
#define NB      16            // batches per group (per warp-iteration)
#define WARPS   8             // warps per block
#define THREADS (WARPS * 32)
#define GPW     2             // groups per warp

__global__ __launch_bounds__(THREADS, 4)
void cone_projection_kernel(const float* __restrict__ eyes,
                            const float* __restrict__ v,
                            const float* __restrict__ R,
                            const float* __restrict__ t,
                            const float* __restrict__ alpha,
                            float* __restrict__ out,
                            int B, int n_groups)
{
    __shared__ float4 scoef[WARPS * NB * 2];   // per batch: (c0,c1,c2,c3),(c4,c5,-,-)

    const int lane = threadIdx.x & 31;
    const int wid  = threadIdx.x >> 5;
    const int gwarp = blockIdx.x * WARPS + wid;         // global warp id
    const int total_warps = gridDim.x * WARPS;

    // --- Per-thread grid geometry for k = lane + 32p, p = 0..5 (30 regs) ---
    float gx2[6], gy2[6], gxy[6], gx[6], gy[6];
    #pragma unroll
    for (int p = 0; p < 6; ++p) {
        const int k  = lane + 32 * p;
        const int ki = (k * 79) >> 10;          // k/13, exact for k < 169
        const int kj = k - 13 * ki;
        const float x = (float)(ki - 6) * (1.0f / 6.0f);
        const float y = (float)(kj - 6) * (1.0f / 6.0f);
        gx2[p] = x * x;  gy2[p] = y * y;  gxy[p] = x * y;
        gx[p]  = x;      gy[p]  = y;
    }

    // --- Grid-stride over batch groups (GPW iterations per warp) ---
    for (int g = gwarp; g < n_groups; g += total_warps) {
        const long long base_b = (long long)g * NB;

        // Phase A: lanes 0..15 build coefficients for their batch
        if (lane < NB) {
            const long long b = base_b + lane;
            if (b < B) {
                float vx = v[b * 3 + 0];
                float vy = v[b * 3 + 1];
                float vz = v[b * 3 + 2];
                float n  = fmaxf(sqrtf(vx * vx + vy * vy + vz * vz), 1e-14f);
                float inv = 1.0f / n;
                vx *= inv; vy *= inv; vz *= inv;

                const float a = alpha[b];

                const float* Rb = R + b * 9;
                const float w0x = Rb[0], w0y = Rb[3], w0z = Rb[6];   // R[:,0]
                const float w1x = Rb[1], w1y = Rb[4], w1z = Rb[7];   // R[:,1]
                const float w2x = t[b * 3 + 0] - eyes[b * 3 + 0];
                const float w2y = t[b * 3 + 1] - eyes[b * 3 + 1];
                const float w2z = t[b * 3 + 2] - eyes[b * 3 + 2];

                const float d0 = vx * w0x + vy * w0y + vz * w0z;
                const float d1 = vx * w1x + vy * w1y + vz * w1z;
                const float d2 = vx * w2x + vy * w2y + vz * w2z;

                const float c0 = d0 * d0 - a * (w0x * w0x + w0y * w0y + w0z * w0z);
                const float c1 = d1 * d1 - a * (w1x * w1x + w1y * w1y + w1z * w1z);
                const float c2 = d2 * d2 - a * (w2x * w2x + w2y * w2y + w2z * w2z);
                const float c3 = 2.0f * (d0 * d1 - a * (w0x * w1x + w0y * w1y + w0z * w1z));
                const float c4 = 2.0f * (d0 * d2 - a * (w0x * w2x + w0y * w2y + w0z * w2z));
                const float c5 = 2.0f * (d1 * d2 - a * (w1x * w2x + w1y * w2y + w1z * w2z));

                const int s = (wid * NB + lane) * 2;
                scoef[s]     = make_float4(c0, c1, c2, c3);
                scoef[s + 1] = make_float4(c4, c5, 0.0f, 0.0f);
            }
        }
        __syncwarp();

        // Phase B: 16 batches x (2 broadcast LDS.128 + 6 x (5 FFMA + STG))
        #pragma unroll 4
        for (int bt = 0; bt < NB; ++bt) {
            const long long b = base_b + bt;
            if (b >= B) break;

            const int s = (wid * NB + bt) * 2;
            const float4 ca = scoef[s];       // c0 c1 c2 c3
            const float4 cb = scoef[s + 1];   // c4 c5 -  -

            float* o = out + b * (long long)K_GRID + lane;

            #pragma unroll
            for (int p = 0; p < 6; ++p) {
                float r = fmaf(ca.x, gx2[p], ca.z);
                r = fmaf(ca.y, gy2[p], r);
                r = fmaf(ca.w, gxy[p], r);
                r = fmaf(cb.x, gx[p],  r);
                r = fmaf(cb.y, gy[p],  r);
                if (p < 5 || lane < K_GRID - 160)   // last pass: k = 160+lane < 169
                    __stcs(&o[p * 32], r);          // streaming (evict-first) store
            }
        }
        __syncwarp();   // protect scoef before next group's phase A overwrite
    }
}

extern "C" void kernel_launch(void* const* d_in, const int* in_sizes, int n_in,
                              void* d_out, int out_size) {
    const float* eyes  = (const float*)d_in[0];
    const float* v     = (const float*)d_in[1];
    const float* R     = (const float*)d_in[2];
    const float* t     = (const float*)d_in[3];
    const float* alpha = (const float*)d_in[4];
    float* out = (float*)d_out;

    const int B = in_sizes[4];                         // alpha: B elements
    const int n_groups = (B + NB - 1) / NB;            // 8192 for B=131072
    // GPW groups per warp -> blocks = groups / (WARPS*GPW); 512 for B=131072,
    // all co-resident at 4 blocks/SM (592 slots on 148 SMs) -> single wave.
    int blocks = (n_groups + WARPS * GPW - 1) / (WARPS * GPW);

    cone_projection_kernel<<<blocks, THREADS>>>(eyes, v, R, t, alpha, out,
                                                B, n_groups);
}

// round 12
// speedup vs baseline: 1.1254x; 1.1254x over previous
#include <cuda_runtime.h>
#include <cuda_bf16.h>

// ConeProjection: out[b,k] = P[k]^T * sigma[b] * P[k]
//   sigma[a][c] = (vn·w_a)(vn·w_c) - alpha*(w_a·w_c)
//   w0 = R[:,0], w1 = R[:,1], w2 = t - eyes, vn = v/max(||v||,1e-14)
//   P[k] = ((ki-6)/6, (kj-6)/6, 1),  k = 13*ki + kj
//
// R6 structure (fastest measured: warp owns 16 batches, grid 1024, geometry
// in registers, coalesced streaming STG.32) with the 6 store passes fused
// into 3 pass-pairs computed by packed fma.rn.f32x2 (FFMA2): one instruction
// = two IEEE FMAs, bitwise identical results. Coefficients are stored
// PRE-DUPLICATED in smem ((c,c) pairs) so phase B needs zero pack ops:
// 3 broadcast LDS.128 deliver the packed f32x2 operands directly.

#define K_GRID  169
#define NB      16            // batches per warp
#define WARPS   8             // warps per block
#define THREADS (WARPS * 32)

__device__ __forceinline__ unsigned long long pack2f(float lo, float hi) {
    unsigned long long d;
    asm("mov.b64 %0, {%1, %2};" : "=l"(d) : "f"(lo), "f"(hi));
    return d;
}
__device__ __forceinline__ unsigned long long fma2(unsigned long long a,
                                                   unsigned long long b,
                                                   unsigned long long c) {
    unsigned long long d;
    asm("fma.rn.f32x2 %0, %1, %2, %3;" : "=l"(d) : "l"(a), "l"(b), "l"(c));
    return d;
}
__device__ __forceinline__ void unpack2f(unsigned long long s, float& lo, float& hi) {
    asm("mov.b64 {%0, %1}, %2;" : "=f"(lo), "=f"(hi) : "l"(s));
}

__global__ __launch_bounds__(THREADS)
void cone_projection_kernel(const float* __restrict__ eyes,
                            const float* __restrict__ v,
                            const float* __restrict__ R,
                            const float* __restrict__ t,
                            const float* __restrict__ alpha,
                            float* __restrict__ out,
                            int B)
{
    // per batch, 3 float4: (c0,c0,c1,c1), (c3,c3,c4,c4), (c5,c5,c2,c2)
    __shared__ float4 scoef[WARPS * NB * 3];

    const int lane = threadIdx.x & 31;
    const int wid  = threadIdx.x >> 5;
    const long long base_b = ((long long)blockIdx.x * WARPS + wid) * NB;

    // --- Packed per-thread geometry for pass-pair pp: elements
    //     k0 = lane + 64*pp (lo), k1 = k0 + 32 (hi); pp = 0..2 (30 regs) ---
    unsigned long long Gx2[3], Gy2[3], Gxy[3], Gx[3], Gy[3];
    #pragma unroll
    for (int pp = 0; pp < 3; ++pp) {
        float xv[2], yv[2];
        #pragma unroll
        for (int h = 0; h < 2; ++h) {
            const int k  = lane + 64 * pp + 32 * h;   // k1 may exceed 168: store predicated off
            const int ki = (k * 79) >> 10;            // k/13, exact for k < 169
            const int kj = k - 13 * ki;
            xv[h] = (float)(ki - 6) * (1.0f / 6.0f);
            yv[h] = (float)(kj - 6) * (1.0f / 6.0f);
        }
        Gx2[pp] = pack2f(xv[0] * xv[0], xv[1] * xv[1]);
        Gy2[pp] = pack2f(yv[0] * yv[0], yv[1] * yv[1]);
        Gxy[pp] = pack2f(xv[0] * yv[0], xv[1] * yv[1]);
        Gx[pp]  = pack2f(xv[0], xv[1]);
        Gy[pp]  = pack2f(yv[0], yv[1]);
    }

    // --- Phase A: lanes 0..15 build duplicated coefficient pairs ---
    if (lane < NB) {
        const long long b = base_b + lane;
        if (b < B) {
            float vx = v[b * 3 + 0];
            float vy = v[b * 3 + 1];
            float vz = v[b * 3 + 2];
            float n  = fmaxf(sqrtf(vx * vx + vy * vy + vz * vz), 1e-14f);
            float inv = 1.0f / n;
            vx *= inv; vy *= inv; vz *= inv;

            const float a = alpha[b];

            const float* Rb = R + b * 9;
            const float w0x = Rb[0], w0y = Rb[3], w0z = Rb[6];   // R[:,0]
            const float w1x = Rb[1], w1y = Rb[4], w1z = Rb[7];   // R[:,1]
            const float w2x = t[b * 3 + 0] - eyes[b * 3 + 0];
            const float w2y = t[b * 3 + 1] - eyes[b * 3 + 1];
            const float w2z = t[b * 3 + 2] - eyes[b * 3 + 2];

            const float d0 = vx * w0x + vy * w0y + vz * w0z;
            const float d1 = vx * w1x + vy * w1y + vz * w1z;
            const float d2 = vx * w2x + vy * w2y + vz * w2z;

            const float c0 = d0 * d0 - a * (w0x * w0x + w0y * w0y + w0z * w0z); // x^2
            const float c1 = d1 * d1 - a * (w1x * w1x + w1y * w1y + w1z * w1z); // y^2
            const float c2 = d2 * d2 - a * (w2x * w2x + w2y * w2y + w2z * w2z); // 1
            const float c3 = 2.0f * (d0 * d1 - a * (w0x * w1x + w0y * w1y + w0z * w1z)); // xy
            const float c4 = 2.0f * (d0 * d2 - a * (w0x * w2x + w0y * w2y + w0z * w2z)); // x
            const float c5 = 2.0f * (d1 * d2 - a * (w1x * w2x + w1y * w2y + w1z * w2z)); // y

            const int s = (wid * NB + lane) * 3;
            scoef[s]     = make_float4(c0, c0, c1, c1);
            scoef[s + 1] = make_float4(c3, c3, c4, c4);
            scoef[s + 2] = make_float4(c5, c5, c2, c2);
        }
    }
    __syncwarp();

    // --- Phase B: 16 batches x (3 broadcast LDS.128 + 3 x (5 FFMA2 + 2 STG)) ---
    const ulonglong2* sc2 = reinterpret_cast<const ulonglong2*>(scoef);

    #pragma unroll 4
    for (int bt = 0; bt < NB; ++bt) {
        const long long b = base_b + bt;
        if (b >= B) break;

        const int s = (wid * NB + bt) * 3;
        const ulonglong2 q0 = sc2[s];       // (c0,c0) , (c1,c1)
        const ulonglong2 q1 = sc2[s + 1];   // (c3,c3) , (c4,c4)
        const ulonglong2 q2 = sc2[s + 2];   // (c5,c5) , (c2,c2)

        float* o = out + b * (long long)K_GRID + lane;

        #pragma unroll
        for (int pp = 0; pp < 3; ++pp) {
            unsigned long long r = fma2(q0.x, Gx2[pp], q2.y);  // c0*x^2 + c2
            r = fma2(q0.y, Gy2[pp], r);                        // + c1*y^2
            r = fma2(q1.x, Gxy[pp], r);                        // + c3*x*y
            r = fma2(q1.y, Gx[pp],  r);                        // + c4*x
            r = fma2(q2.x, Gy[pp],  r);                        // + c5*y
            float rlo, rhi;
            unpack2f(r, rlo, rhi);
            __stcs(&o[64 * pp], rlo);                 // pass 2*pp   (always valid)
            if (pp < 2 || lane < K_GRID - 160)        // pass 5: k = 160+lane < 169
                __stcs(&o[64 * pp + 32], rhi);        // pass 2*pp+1
        }
    }
}

extern "C" void kernel_launch(void* const* d_in, const int* in_sizes, int n_in,
                              void* d_out, int out_size) {
    const float* eyes  = (const float*)d_in[0];
    const float* v     = (const float*)d_in[1];
    const float* R     = (const float*)d_in[2];
    const float* t     = (const float*)d_in[3];
    const float* alpha = (const float*)d_in[4];
    float* out = (float*)d_out;

    const int B = in_sizes[4];                            // alpha: B elements
    const int warp_groups = (B + NB - 1) / NB;            // 8192 for B=131072
    const int blocks = (warp_groups + WARPS - 1) / WARPS; // 1024

    cone_projection_kernel<<<blocks, THREADS>>>(eyes, v, R, t, alpha, out, B);
}